// round 16
// baseline (speedup 1.0000x reference)
#include <cuda_runtime.h>
#include <cstdint>

// Problem constants
#define DD    256
#define HW    4096
#define NTOK  65536          // 16 * 4096
#define KCB   2048
#define QSIZE 16777216       // 16 * 256 * 4096
// out layout (float32): [0..QSIZE) q, [QSIZE] loss, [QSIZE+1] codebook_loss,
// [QSIZE+2] commitment_loss, [QSIZE+3 .. +KCB) counts

#define EPS_SEL 2.0e-3f      // >= 3x worst-case int8 score error (~6e-4)
#define CAND    32
#define APITCH  68           // uints per 256B row (272B pitch, 16B aligned)

// Scratch (device globals — no allocs allowed)
__device__ float    g_c2[KCB];
__device__ float    g_csc[KCB];              // cmax/127 (reconstruct scale)
__device__ float    g_z2[NTOK];
__device__ float    g_zsc[NTOK];             // zmax/127
__device__ float    g_zt[(size_t)NTOK * DD]; // z fp32 token-major (64 MB)
__device__ uint32_t g_qzt[(size_t)NTOK * 64];// z int8 quads token-major (16 MB)
__device__ uint32_t g_qc[(size_t)KCB * 64];  // codebook int8 quads (512 KB)
__device__ int      g_ccnt[NTOK];
__device__ int      g_cand[(size_t)NTOK * CAND];
__device__ int      g_idx[NTOK];

// ---------------------------------------------------------------------------
__device__ __forceinline__ uint32_t smem_u32(const void* p) {
    uint32_t a;
    asm("{ .reg .u64 t; cvta.to.shared.u64 t, %1; cvt.u32.u64 %0, t; }"
        : "=r"(a) : "l"(p));
    return a;
}
__device__ __forceinline__ void cp16(uint32_t dst, const void* src) {
    asm volatile("cp.async.ca.shared.global [%0], [%1], 16;"
                 :: "r"(dst), "l"(src) : "memory");
}
#define CP_COMMIT() asm volatile("cp.async.commit_group;" ::: "memory")
#define CP_WAIT0()  asm volatile("cp.async.wait_group 0;" ::: "memory")

__device__ __forceinline__ uint32_t pack4(float a, float b, float c, float d,
                                          float inv) {
    int q0 = max(-127, min(127, __float2int_rn(a * inv)));
    int q1 = max(-127, min(127, __float2int_rn(b * inv)));
    int q2 = max(-127, min(127, __float2int_rn(c * inv)));
    int q3 = max(-127, min(127, __float2int_rn(d * inv)));
    return (uint32_t)(q0 & 255) | ((uint32_t)(q1 & 255) << 8) |
           ((uint32_t)(q2 & 255) << 16) | ((uint32_t)q3 << 24);
}

// exact fp32 rescore — byte-identical to rounds 7/14/15 (argmins == reference)
__device__ __forceinline__ unsigned long long rescore(int n, int k,
                                                      const float* __restrict__ cb) {
    const float4* zp = (const float4*)(g_zt + (size_t)n * DD);
    const float4* cr = (const float4*)(cb + (size_t)k * DD);
    float s0 = 0.f, s1 = 0.f, s2 = 0.f, s3 = 0.f;
    #pragma unroll 8
    for (int i = 0; i < 64; i++) {
        float4 a = zp[i], b = cr[i];
        s0 = fmaf(a.x, b.x, s0); s1 = fmaf(a.y, b.y, s1);
        s2 = fmaf(a.z, b.z, s2); s3 = fmaf(a.w, b.w, s3);
    }
    float dot  = (s0 + s1) + (s2 + s3);
    float dist = fmaf(-2.0f, dot, g_z2[n] + g_c2[k]);
    return ((unsigned long long)__float_as_uint(dist) << 32) | (unsigned)k;
}

// ---------------------------------------------------------------------------
__global__ void init_kernel(float* out) {
    int i = threadIdx.x + blockIdx.x * blockDim.x;
    if (i < 3 + KCB) out[QSIZE + i] = 0.0f;
    if (i < NTOK) g_ccnt[i] = 0;
}

// c2 + per-code max (one warp per code)
__global__ void c2_kernel(const float* __restrict__ cb) {
    int warp = (threadIdx.x >> 5) + blockIdx.x * (blockDim.x >> 5);
    int lane = threadIdx.x & 31;
    if (warp >= KCB) return;
    const float* row = cb + (size_t)warp * DD;
    float s = 0.f, mx = 0.f;
    #pragma unroll
    for (int d = lane; d < DD; d += 32) {
        float v = row[d];
        s = fmaf(v, v, s);
        mx = fmaxf(mx, fabsf(v));
    }
    #pragma unroll
    for (int off = 16; off; off >>= 1) {
        s += __shfl_down_sync(0xffffffffu, s, off);
        mx = fmaxf(mx, __shfl_down_sync(0xffffffffu, mx, off));
    }
    if (lane == 0) {
        g_c2[warp]  = s;
        g_csc[warp] = (mx > 0.f) ? mx * (1.0f / 127.0f) : 1.0f;
    }
}

// z2 + per-token max (sequential fp32 sum — must match reference rounding)
__global__ void z2_kernel(const float* __restrict__ z) {
    int n = threadIdx.x + blockIdx.x * blockDim.x;
    if (n >= NTOK) return;
    int b = n >> 12, hw = n & 4095;
    const float* p = z + (size_t)b * (DD * HW) + hw;
    float s = 0.f, mx = 0.f;
    #pragma unroll 8
    for (int d = 0; d < DD; d++) {
        float v = p[(size_t)d * HW];
        s = fmaf(v, v, s);
        mx = fmaxf(mx, fabsf(v));
    }
    g_z2[n]  = s;
    g_zsc[n] = (mx > 0.f) ? mx * (1.0f / 127.0f) : 1.0f;
}

// transpose z -> token-major fp32 (g_zt) + fused int8 quantization (g_qzt).
// Requires g_zsc (z2_kernel runs first).
__global__ __launch_bounds__(256)
void tz_kernel(const float* __restrict__ z) {
    __shared__ float t[64][65];
    const int bx = blockIdx.x;
    const int hw0 = (bx & 63) * 64;
    const int d0  = ((bx >> 6) & 3) * 64;
    const int b   = bx >> 8;
    const float* zb = z + (size_t)b * (DD * HW);
    const int tid = threadIdx.x;
    #pragma unroll
    for (int it = 0; it < 16; it++) {
        int p = tid + it * 256;
        int dd = p >> 6, r = p & 63;
        t[dd][r] = zb[(size_t)(d0 + dd) * HW + hw0 + r];
    }
    __syncthreads();
    #pragma unroll
    for (int it = 0; it < 16; it++) {
        int p = tid + it * 256;
        int r = p >> 6, dd = p & 63;
        size_t n = (size_t)b * 4096 + hw0 + r;
        g_zt[n * 256 + d0 + dd] = t[dd][r];
    }
    // fused quantization: 64 tokens x 16 quads (of this 64-d slice)
    #pragma unroll
    for (int it = 0; it < 4; it++) {
        int p = tid + it * 256;
        int tok = p >> 4, qq = p & 15;
        int n = b * 4096 + hw0 + tok;
        float inv = 127.0f * __frcp_rn(g_zsc[n] * 127.0f);  // == 1/zsc
        int dl = qq * 4;
        uint32_t q = pack4(t[dl + 0][tok], t[dl + 1][tok],
                           t[dl + 2][tok], t[dl + 3][tok], inv);
        g_qzt[(size_t)n * 64 + (d0 >> 2) + qq] = q;
    }
}

// quantize codebook -> int8 quads g_qc[k][64]
__global__ void qc_kernel(const float* __restrict__ cb) {
    int idx = threadIdx.x + blockIdx.x * blockDim.x;   // 2048 * 64
    if (idx >= KCB * 64) return;
    int k = idx >> 6, dq = idx & 63;
    float inv = 127.0f * __frcp_rn(g_csc[k] * 127.0f);
    const float4 v = *(const float4*)(cb + (size_t)k * 256 + dq * 4);
    g_qc[idx] = pack4(v.x, v.y, v.z, v.w, inv);
}

// ---------------------------------------------------------------------------
// Filter kernel: 128 tokens/CTA x 2048 codes via DP4A (exact int32 acc).
// A tile resident in smem for the whole kernel; B double-buffered (cp.async);
// K-major rows + LDS.64 -> 16 LDS per 128 DP4A. Two-phase chunk epilogue.
// ---------------------------------------------------------------------------
#define SMF_A     0                     // 128 * 272B = 34816
#define SMF_B0    34816
#define SMF_B1    69632
#define SMF_MIN   104448                // 128 floats
#define SMF_TOTAL 104960

__global__ __launch_bounds__(256, 2)
void vq_filter_kernel() {
    extern __shared__ uint32_t smf[];
    uint32_t* smA = smf;                              // [128][APITCH]
    float* sm_min = (float*)((char*)smf + SMF_MIN);
    const uint32_t sbase = smem_u32(smf);

    const int tid = threadIdx.x;
    const int tx = tid & 15;
    const int ty = tid >> 4;
    const int n0 = blockIdx.x * 128;

    // load A once (2 rows / warp, fully coalesced)
    #pragma unroll
    for (int it = 0; it < 8; it++) {
        int p = tid + it * 256;        // 128 rows x 16 quad-groups
        int r = p >> 4, c = p & 15;
        uint4 v = *(const uint4*)(g_qzt + (size_t)(n0 + r) * 64 + c * 4);
        *(uint4*)(smA + r * APITCH + c * 4) = v;
    }
    if (tid < 128) sm_min[tid] = __int_as_float(0x7f800000);

    float zs2[8];
    #pragma unroll
    for (int i = 0; i < 8; i++) zs2[i] = 2.0f * g_zsc[n0 + ty + 16 * i];

    // stage B chunk 0
    #pragma unroll
    for (int it = 0; it < 8; it++) {
        int p = tid + it * 256;
        int r = p >> 4, c = p & 15;
        cp16(sbase + SMF_B0 + r * 272 + c * 16,
             g_qc + (size_t)r * 64 + c * 4);
    }
    CP_COMMIT();
    CP_WAIT0();
    __syncthreads();

    for (int kc = 0; kc < 16; kc++) {
        const uint32_t* smB = smf + ((kc & 1) ? SMF_B1 : SMF_B0) / 4;

        // stage next chunk into the other buffer (its prior contents were
        // fully consumed before last iteration's __syncthreads)
        if (kc < 15) {
            const uint32_t dstb = sbase + ((kc & 1) ? SMF_B0 : SMF_B1);
            #pragma unroll
            for (int it = 0; it < 8; it++) {
                int p = tid + it * 256;
                int r = p >> 4, c = p & 15;
                cp16(dstb + r * 272 + c * 16,
                     g_qc + (size_t)((kc + 1) * 128 + r) * 64 + c * 4);
            }
            CP_COMMIT();
        }

        int acc[8][8];
        #pragma unroll
        for (int i = 0; i < 8; i++)
            #pragma unroll
            for (int j = 0; j < 8; j++) acc[i][j] = 0;

        #pragma unroll 4
        for (int dq2 = 0; dq2 < 32; dq2++) {
            uint2 a2[8], b2[8];
            #pragma unroll
            for (int i = 0; i < 8; i++)
                a2[i] = *(const uint2*)(smA + (ty + 16 * i) * APITCH + dq2 * 2);
            #pragma unroll
            for (int j = 0; j < 8; j++)
                b2[j] = *(const uint2*)(smB + (tx + 16 * j) * APITCH + dq2 * 2);
            #pragma unroll
            for (int i = 0; i < 8; i++)
                #pragma unroll
                for (int j = 0; j < 8; j++) {
                    acc[i][j] = __dp4a((int)a2[i].x, (int)b2[j].x, acc[i][j]);
                    acc[i][j] = __dp4a((int)a2[i].y, (int)b2[j].y, acc[i][j]);
                }
        }

        // phase 1: scores + chunk-wide per-token min
        float sc[8][8];
        float tmin[8];
        #pragma unroll
        for (int i = 0; i < 8; i++) {
            float mn = __int_as_float(0x7f800000);
            #pragma unroll
            for (int j = 0; j < 8; j++) {
                const int k = kc * 128 + tx + 16 * j;
                float s = fmaf(-zs2[i] * g_csc[k], (float)acc[i][j], g_c2[k]);
                sc[i][j] = s;
                mn = fminf(mn, s);
            }
            #pragma unroll
            for (int off = 1; off < 16; off <<= 1)
                mn = fminf(mn, __shfl_xor_sync(0xffffffffu, mn, off, 16));
            tmin[i] = fminf(mn, sm_min[ty + 16 * i]);
        }

        // phase 2: append candidates within EPS of the prefix+chunk min
        #pragma unroll
        for (int i = 0; i < 8; i++) {
            const float thr = tmin[i] + EPS_SEL;
            #pragma unroll
            for (int j = 0; j < 8; j++) {
                if (sc[i][j] <= thr) {
                    const int n = n0 + ty + 16 * i;
                    int slot = atomicAdd(&g_ccnt[n], 1);
                    if (slot < CAND)
                        g_cand[(size_t)n * CAND + slot] = kc * 128 + tx + 16 * j;
                }
            }
            if (tx == 0) sm_min[ty + 16 * i] = tmin[i];   // all lanes agree
        }

        if (kc < 15) CP_WAIT0();
        __syncthreads();
    }
}

// ---------------------------------------------------------------------------
// Rescore kernel: one warp per token; exact fp32 dist, (bits<<32)|k min =>
// first-index tie-break. Overflow (cnt > CAND) -> full exact scan.
// ---------------------------------------------------------------------------
__global__ __launch_bounds__(256)
void vq_rescore_kernel(const float* __restrict__ cb) {
    const int lane = threadIdx.x & 31;
    const int n = blockIdx.x * 8 + (threadIdx.x >> 5);
    const int cnt = g_ccnt[n];

    unsigned long long key = ~0ULL;
    if (cnt <= CAND) {
        for (int c = lane; c < cnt; c += 32) {
            unsigned long long x = rescore(n, g_cand[(size_t)n * CAND + c], cb);
            if (x < key) key = x;
        }
    } else {
        for (int k = lane; k < KCB; k += 32) {
            unsigned long long x = rescore(n, k, cb);
            if (x < key) key = x;
        }
    }
    #pragma unroll
    for (int off = 16; off; off >>= 1) {
        unsigned long long x = __shfl_xor_sync(0xffffffffu, key, off);
        if (x < key) key = x;
    }
    if (lane == 0) g_idx[n] = (int)(key & 0xFFFFFFFFu);
}

// ---------------------------------------------------------------------------
// Output epilogue: q (straight-through), counts, fused SSE
// ---------------------------------------------------------------------------
__global__ __launch_bounds__(256)
void vq_out_kernel(const float* __restrict__ z, const float* __restrict__ cb,
                   float* __restrict__ out) {
    __shared__ float lred[8];
    const int tid = threadIdx.x;
    const int n0 = blockIdx.x * 128;
    const int b = n0 >> 12, hw0 = n0 & 4095;

    if (tid < 128) atomicAdd(out + QSIZE + 3 + g_idx[n0 + tid], 1.0f);

    const int tok  = tid & 127;
    const int half = tid >> 7;
    const int kidx = g_idx[n0 + tok];
    const float* crow = cb + (size_t)kidx * DD;
    float* qbase = out + (size_t)b * (DD * HW) + hw0 + tok;
    const float* zb2 = z + (size_t)b * (DD * HW) + hw0 + tok;
    float lsum = 0.f;
    #pragma unroll 4
    for (int d = half * 128; d < half * 128 + 128; d++) {
        float c  = crow[d];
        float zz = zb2[(size_t)d * HW];
        float df = zz - c;
        lsum = fmaf(df, df, lsum);
        qbase[(size_t)d * HW] = zz + (c - zz);   // == reference ST rounding
    }
    #pragma unroll
    for (int off = 16; off; off >>= 1) lsum += __shfl_down_sync(0xffffffffu, lsum, off);
    if ((tid & 31) == 0) lred[tid >> 5] = lsum;
    __syncthreads();
    if (tid == 0) {
        float s = 0.f;
        #pragma unroll
        for (int w = 0; w < 8; w++) s += lred[w];
        atomicAdd(out + QSIZE + 1, s);
    }
}

__global__ void finalize_kernel(float* out) {
    float sse = out[QSIZE + 1];
    float mse = sse / (float)((size_t)NTOK * DD);
    out[QSIZE]     = fmaf(0.25f, mse, mse);
    out[QSIZE + 1] = mse;
    out[QSIZE + 2] = mse;
}

// ---------------------------------------------------------------------------
extern "C" void kernel_launch(void* const* d_in, const int* in_sizes, int n_in,
                              void* d_out, int out_size) {
    const float* z  = (const float*)d_in[0];     // (16, 256, 64, 64)
    const float* cb = (const float*)d_in[1];     // (2048, 256)
    float* out = (float*)d_out;

    cudaFuncSetAttribute(vq_filter_kernel,
                         cudaFuncAttributeMaxDynamicSharedMemorySize, SMF_TOTAL);

    init_kernel<<<NTOK / 256 + 9, 256>>>(out);
    c2_kernel<<<KCB / 8, 256>>>(cb);
    z2_kernel<<<NTOK / 256, 256>>>(z);
    tz_kernel<<<4096, 256>>>(z);
    qc_kernel<<<KCB * 64 / 256, 256>>>(cb);
    vq_filter_kernel<<<NTOK / 128, 256, SMF_TOTAL>>>();
    vq_rescore_kernel<<<NTOK / 8, 256>>>(cb);
    vq_out_kernel<<<NTOK / 128, 256>>>(z, cb, out);
    finalize_kernel<<<1, 1>>>(out);
}

// round 17
// speedup vs baseline: 1.6515x; 1.6515x over previous
#include <cuda_runtime.h>
#include <cstdint>

// Problem constants
#define DD    256
#define HW    4096
#define NTOK  65536          // 16 * 4096
#define KCB   2048
#define QSIZE 16777216       // 16 * 256 * 4096
// out layout (float32): [0..QSIZE) q, [QSIZE] loss, [QSIZE+1] codebook_loss,
// [QSIZE+2] commitment_loss, [QSIZE+3 .. +KCB) counts

#define EPS_SEL 2.0e-3f      // >= 3x worst-case int8 score error (~6e-4)
#define CAND    32

// Scratch (device globals — no allocs allowed)
__device__ float    g_c2[KCB];
__device__ float    g_csc[KCB];              // cmax/127 (reconstruct scale)
__device__ float    g_z2[NTOK];
__device__ float    g_zsc[NTOK];             // zmax/127
__device__ float    g_zt[(size_t)NTOK * DD]; // z fp32 token-major (64 MB)
__device__ uint32_t g_qzp[64u * NTOK];       // z int8 quads, plane-major (16 MB)
__device__ uint32_t g_qcp[64 * KCB];         // codebook quads, plane-major (512 KB)
__device__ int      g_ccnt[NTOK];
__device__ int      g_cand[(size_t)NTOK * CAND];
__device__ int      g_idx[NTOK];

// ---------------------------------------------------------------------------
__device__ __forceinline__ uint32_t pack4(float a, float b, float c, float d,
                                          float inv) {
    int q0 = max(-127, min(127, __float2int_rn(a * inv)));
    int q1 = max(-127, min(127, __float2int_rn(b * inv)));
    int q2 = max(-127, min(127, __float2int_rn(c * inv)));
    int q3 = max(-127, min(127, __float2int_rn(d * inv)));
    return (uint32_t)(q0 & 255) | ((uint32_t)(q1 & 255) << 8) |
           ((uint32_t)(q2 & 255) << 16) | ((uint32_t)q3 << 24);
}

// exact fp32 rescore — byte-identical to rounds 7/14/15/16 (argmins == ref)
__device__ __forceinline__ unsigned long long rescore(int n, int k,
                                                      const float* __restrict__ cb) {
    const float4* zp = (const float4*)(g_zt + (size_t)n * DD);
    const float4* cr = (const float4*)(cb + (size_t)k * DD);
    float s0 = 0.f, s1 = 0.f, s2 = 0.f, s3 = 0.f;
    #pragma unroll 8
    for (int i = 0; i < 64; i++) {
        float4 a = zp[i], b = cr[i];
        s0 = fmaf(a.x, b.x, s0); s1 = fmaf(a.y, b.y, s1);
        s2 = fmaf(a.z, b.z, s2); s3 = fmaf(a.w, b.w, s3);
    }
    float dot  = (s0 + s1) + (s2 + s3);
    float dist = fmaf(-2.0f, dot, g_z2[n] + g_c2[k]);
    return ((unsigned long long)__float_as_uint(dist) << 32) | (unsigned)k;
}

// ---------------------------------------------------------------------------
__global__ void init_kernel(float* out) {
    int i = threadIdx.x + blockIdx.x * blockDim.x;
    if (i < 3 + KCB) out[QSIZE + i] = 0.0f;
    if (i < NTOK) g_ccnt[i] = 0;
}

// c2 + per-code max (one warp per code)
__global__ void c2_kernel(const float* __restrict__ cb) {
    int warp = (threadIdx.x >> 5) + blockIdx.x * (blockDim.x >> 5);
    int lane = threadIdx.x & 31;
    if (warp >= KCB) return;
    const float* row = cb + (size_t)warp * DD;
    float s = 0.f, mx = 0.f;
    #pragma unroll
    for (int d = lane; d < DD; d += 32) {
        float v = row[d];
        s = fmaf(v, v, s);
        mx = fmaxf(mx, fabsf(v));
    }
    #pragma unroll
    for (int off = 16; off; off >>= 1) {
        s += __shfl_down_sync(0xffffffffu, s, off);
        mx = fmaxf(mx, __shfl_down_sync(0xffffffffu, mx, off));
    }
    if (lane == 0) {
        g_c2[warp]  = s;
        g_csc[warp] = (mx > 0.f) ? mx * (1.0f / 127.0f) : 1.0f;
    }
}

// z2 + per-token max (sequential fp32 sum — must match reference rounding)
__global__ void z2_kernel(const float* __restrict__ z) {
    int n = threadIdx.x + blockIdx.x * blockDim.x;
    if (n >= NTOK) return;
    int b = n >> 12, hw = n & 4095;
    const float* p = z + (size_t)b * (DD * HW) + hw;
    float s = 0.f, mx = 0.f;
    #pragma unroll 8
    for (int d = 0; d < DD; d++) {
        float v = p[(size_t)d * HW];
        s = fmaf(v, v, s);
        mx = fmaxf(mx, fabsf(v));
    }
    g_z2[n]  = s;
    g_zsc[n] = (mx > 0.f) ? mx * (1.0f / 127.0f) : 1.0f;
}

// transpose z -> token-major fp32 (g_zt) + fused int8 quantization into
// plane-major g_qzp (coalesced writes). Requires g_zsc (z2 first).
__global__ __launch_bounds__(256)
void tz_kernel(const float* __restrict__ z) {
    __shared__ float t[64][65];
    const int bx = blockIdx.x;
    const int hw0 = (bx & 63) * 64;
    const int d0  = ((bx >> 6) & 3) * 64;
    const int b   = bx >> 8;
    const float* zb = z + (size_t)b * (DD * HW);
    const int tid = threadIdx.x;
    #pragma unroll
    for (int it = 0; it < 16; it++) {
        int p = tid + it * 256;
        int dd = p >> 6, r = p & 63;
        t[dd][r] = zb[(size_t)(d0 + dd) * HW + hw0 + r];
    }
    __syncthreads();
    #pragma unroll
    for (int it = 0; it < 16; it++) {
        int p = tid + it * 256;
        int r = p >> 6, dd = p & 63;
        size_t n = (size_t)b * 4096 + hw0 + r;
        g_zt[n * 256 + d0 + dd] = t[dd][r];
    }
    // fused quantization: lanes map to consecutive tokens -> coalesced writes
    #pragma unroll
    for (int it = 0; it < 4; it++) {
        int p = tid + it * 256;
        int tok = p & 63, qq = p >> 6;          // qq: 0..15
        int n = b * 4096 + hw0 + tok;
        float inv = 127.0f * __frcp_rn(g_zsc[n] * 127.0f);  // == 1/zsc
        int dl = qq * 4;
        uint32_t q = pack4(t[dl + 0][tok], t[dl + 1][tok],
                           t[dl + 2][tok], t[dl + 3][tok], inv);
        g_qzp[(size_t)((d0 >> 2) + qq) * NTOK + n] = q;
    }
}

// quantize codebook -> plane-major quads g_qcp[dq][k]
__global__ void qc_kernel(const float* __restrict__ cb) {
    int idx = threadIdx.x + blockIdx.x * blockDim.x;   // 2048 * 64
    if (idx >= KCB * 64) return;
    int k = idx >> 6, dq = idx & 63;
    float inv = 127.0f * __frcp_rn(g_csc[k] * 127.0f);
    const float4 v = *(const float4*)(cb + (size_t)k * 256 + dq * 4);
    g_qcp[dq * KCB + k] = pack4(v.x, v.y, v.z, v.w, inv);
}

// ---------------------------------------------------------------------------
// Filter kernel: 128 tokens/CTA x 2048 codes via DP4A (exact int32 acc).
// Plane-major smem (round-15 proven conflict-free), A resident, B staged
// whole-chunk (2 syncs/chunk). Scores overwrite acc in place (no extra regs).
// ---------------------------------------------------------------------------
#define FPITCH    132
#define SMF_A     0                         // 64*132*4 = 33792
#define SMF_B     33792                     // 64*132*4 = 33792
#define SMF_MIN   67584                     // 128 floats
#define SMF_TOTAL 68096

__global__ __launch_bounds__(256, 2)
void vq_filter_kernel() {
    extern __shared__ uint32_t smf[];
    uint32_t* smA = smf;                               // [64][FPITCH]
    uint32_t* smB = smf + SMF_B / 4;                   // [64][FPITCH]
    float* sm_min = (float*)((char*)smf + SMF_MIN);

    const int tid = threadIdx.x;
    const int tx = tid & 15;
    const int ty = tid >> 4;
    const int n0 = blockIdx.x * 128;

    // stage A once: plane-major, coalesced LDG.128 + conflict-free STS.128
    #pragma unroll
    for (int it = 0; it < 8; it++) {
        int p = tid + it * 256;                        // 64 planes x 32 groups
        int dq = p >> 5, t = p & 31;
        uint4 v = *(const uint4*)(g_qzp + (size_t)dq * NTOK + n0 + 4 * t);
        *(uint4*)(smA + dq * FPITCH + 4 * t) = v;
    }
    if (tid < 128) sm_min[tid] = __int_as_float(0x7f800000);

    float zs2[8];
    #pragma unroll
    for (int i = 0; i < 8; i++) zs2[i] = 2.0f * g_zsc[n0 + ty + 16 * i];

    __syncthreads();

    for (int kc = 0; kc < 16; kc++) {
        // stage B chunk: 64 planes x 128 codes
        #pragma unroll
        for (int it = 0; it < 8; it++) {
            int p = tid + it * 256;
            int dq = p >> 5, t = p & 31;
            uint4 v = *(const uint4*)(g_qcp + dq * KCB + kc * 128 + 4 * t);
            *(uint4*)(smB + dq * FPITCH + 4 * t) = v;
        }
        __syncthreads();

        int acc[8][8];
        #pragma unroll
        for (int i = 0; i < 8; i++)
            #pragma unroll
            for (int j = 0; j < 8; j++) acc[i][j] = 0;

        #pragma unroll 4
        for (int dq = 0; dq < 64; dq++) {
            uint32_t a[8], b[8];
            #pragma unroll
            for (int i = 0; i < 8; i++) a[i] = smA[dq * FPITCH + ty + 16 * i];
            #pragma unroll
            for (int j = 0; j < 8; j++) b[j] = smB[dq * FPITCH + tx + 16 * j];
            #pragma unroll
            for (int i = 0; i < 8; i++)
                #pragma unroll
                for (int j = 0; j < 8; j++)
                    acc[i][j] = __dp4a((int)a[i], (int)b[j], acc[i][j]);
        }

        // phase 1: scores (overwrite acc with float bits) + per-token min
        float tmin[8];
        #pragma unroll
        for (int i = 0; i < 8; i++) tmin[i] = __int_as_float(0x7f800000);
        #pragma unroll
        for (int j = 0; j < 8; j++) {
            const int k = kc * 128 + tx + 16 * j;
            const float cs  = g_csc[k];
            const float c2k = g_c2[k];
            #pragma unroll
            for (int i = 0; i < 8; i++) {
                float s = fmaf(-zs2[i] * cs, (float)acc[i][j], c2k);
                acc[i][j] = __float_as_int(s);
                tmin[i] = fminf(tmin[i], s);
            }
        }
        #pragma unroll
        for (int i = 0; i < 8; i++) {
            #pragma unroll
            for (int off = 1; off < 16; off <<= 1)
                tmin[i] = fminf(tmin[i],
                                __shfl_xor_sync(0xffffffffu, tmin[i], off, 16));
            tmin[i] = fminf(tmin[i], sm_min[ty + 16 * i]);
        }

        // phase 2: append candidates within EPS of the prefix+chunk min
        #pragma unroll
        for (int i = 0; i < 8; i++) {
            const float thr = tmin[i] + EPS_SEL;
            #pragma unroll
            for (int j = 0; j < 8; j++) {
                if (__int_as_float(acc[i][j]) <= thr) {
                    const int n = n0 + ty + 16 * i;
                    int slot = atomicAdd(&g_ccnt[n], 1);
                    if (slot < CAND)
                        g_cand[(size_t)n * CAND + slot] = kc * 128 + tx + 16 * j;
                }
            }
            if (tx == 0) sm_min[ty + 16 * i] = tmin[i];   // all lanes agree
        }
        __syncthreads();   // smB fully consumed before next chunk overwrites
    }
}

// ---------------------------------------------------------------------------
// Rescore kernel: one warp per token; exact fp32 dist, (bits<<32)|k min =>
// first-index tie-break. Overflow (cnt > CAND) -> full exact scan.
// ---------------------------------------------------------------------------
__global__ __launch_bounds__(256)
void vq_rescore_kernel(const float* __restrict__ cb) {
    const int lane = threadIdx.x & 31;
    const int n = blockIdx.x * 8 + (threadIdx.x >> 5);
    const int cnt = g_ccnt[n];

    unsigned long long key = ~0ULL;
    if (cnt <= CAND) {
        for (int c = lane; c < cnt; c += 32) {
            unsigned long long x = rescore(n, g_cand[(size_t)n * CAND + c], cb);
            if (x < key) key = x;
        }
    } else {
        for (int k = lane; k < KCB; k += 32) {
            unsigned long long x = rescore(n, k, cb);
            if (x < key) key = x;
        }
    }
    #pragma unroll
    for (int off = 16; off; off >>= 1) {
        unsigned long long x = __shfl_xor_sync(0xffffffffu, key, off);
        if (x < key) key = x;
    }
    if (lane == 0) g_idx[n] = (int)(key & 0xFFFFFFFFu);
}

// ---------------------------------------------------------------------------
// Output epilogue: q (straight-through), counts, fused SSE
// ---------------------------------------------------------------------------
__global__ __launch_bounds__(256)
void vq_out_kernel(const float* __restrict__ z, const float* __restrict__ cb,
                   float* __restrict__ out) {
    __shared__ float lred[8];
    const int tid = threadIdx.x;
    const int n0 = blockIdx.x * 128;
    const int b = n0 >> 12, hw0 = n0 & 4095;

    if (tid < 128) atomicAdd(out + QSIZE + 3 + g_idx[n0 + tid], 1.0f);

    const int tok  = tid & 127;
    const int half = tid >> 7;
    const int kidx = g_idx[n0 + tok];
    const float* crow = cb + (size_t)kidx * DD;
    float* qbase = out + (size_t)b * (DD * HW) + hw0 + tok;
    const float* zb2 = z + (size_t)b * (DD * HW) + hw0 + tok;
    float lsum = 0.f;
    #pragma unroll 4
    for (int d = half * 128; d < half * 128 + 128; d++) {
        float c  = crow[d];
        float zz = zb2[(size_t)d * HW];
        float df = zz - c;
        lsum = fmaf(df, df, lsum);
        qbase[(size_t)d * HW] = zz + (c - zz);   // == reference ST rounding
    }
    #pragma unroll
    for (int off = 16; off; off >>= 1) lsum += __shfl_down_sync(0xffffffffu, lsum, off);
    if ((tid & 31) == 0) lred[tid >> 5] = lsum;
    __syncthreads();
    if (tid == 0) {
        float s = 0.f;
        #pragma unroll
        for (int w = 0; w < 8; w++) s += lred[w];
        atomicAdd(out + QSIZE + 1, s);
    }
}

__global__ void finalize_kernel(float* out) {
    float sse = out[QSIZE + 1];
    float mse = sse / (float)((size_t)NTOK * DD);
    out[QSIZE]     = fmaf(0.25f, mse, mse);
    out[QSIZE + 1] = mse;
    out[QSIZE + 2] = mse;
}

// ---------------------------------------------------------------------------
extern "C" void kernel_launch(void* const* d_in, const int* in_sizes, int n_in,
                              void* d_out, int out_size) {
    const float* z  = (const float*)d_in[0];     // (16, 256, 64, 64)
    const float* cb = (const float*)d_in[1];     // (2048, 256)
    float* out = (float*)d_out;

    cudaFuncSetAttribute(vq_filter_kernel,
                         cudaFuncAttributeMaxDynamicSharedMemorySize, SMF_TOTAL);

    init_kernel<<<NTOK / 256 + 9, 256>>>(out);
    c2_kernel<<<KCB / 8, 256>>>(cb);
    z2_kernel<<<NTOK / 256, 256>>>(z);
    tz_kernel<<<4096, 256>>>(z);
    qc_kernel<<<KCB * 64 / 256, 256>>>(cb);
    vq_filter_kernel<<<NTOK / 128, 256, SMF_TOTAL>>>();
    vq_rescore_kernel<<<NTOK / 8, 256>>>(cb);
    vq_out_kernel<<<NTOK / 128, 256>>>(z, cb, out);
    finalize_kernel<<<1, 1>>>(out);
}